// round 15
// baseline (speedup 1.0000x reference)
#include <cuda_runtime.h>

// MedianPool2d 3x3, stride 1, reflect pad (1,1,1,1)
// float32 [16, 3, 512, 512] -> same shape.
//
// R15: 4-tile vertical strip per block with register row-carry.
// Each block (128 thr x 4 cols = full 512 width) processes 4 consecutive
// row-pair tiles (8 output rows). Between tiles the two newest input rows
// are CARRIED IN REGISTERS (they are exactly the next tile's f0/f1), so each
// tile after the first needs only 2 vector loads + 4 shuffles instead of
// 4 + 8. No prefetch double-buffering (that killed R8 via registers).
// Math body = champion R7: packed f32x2 compare-exchange vertical stage
// (FMA pipe), scalar FMNMX sliding-window horizontal combine (ALU pipe),
// SHFL halos with merged lane-0/31 fixup, 32-bit offsets.

#define W 512
#define H 512
#define K_TILES 4            // row-pair tiles per block

typedef unsigned long long u64;
typedef unsigned int u32;

__device__ __forceinline__ u64 pk(float x, float y) {
    u64 r; asm("mov.b64 %0, {%1, %2};" : "=l"(r) : "f"(x), "f"(y)); return r;
}
__device__ __forceinline__ float2 upk(u64 v) {
    float2 f; asm("mov.b64 {%0, %1}, %2;" : "=f"(f.x), "=f"(f.y) : "l"(v)); return f;
}

// packed compare-exchange on 2 fp32 lanes: lo=min, hi=max (FMA pipe)
__device__ __forceinline__ void cex2(u64 a, u64 b, u64& lo, u64& hi) {
    const u64 n1 = 0xBF800000BF800000ULL;
    const u64 hf = 0x3F0000003F000000ULL;
    const u64 nh = 0xBF000000BF000000ULL;
    u64 s, d, k, h;
    asm("add.rn.f32x2 %0, %1, %2;" : "=l"(s) : "l"(a), "l"(b));
    asm("fma.rn.f32x2 %0, %1, %2, %3;" : "=l"(d) : "l"(b), "l"(n1), "l"(a)); // a-b
    k = d & 0x7FFFFFFF7FFFFFFFULL;                                           // |a-b|
    asm("mul.rn.f32x2 %0, %1, %2;" : "=l"(h) : "l"(s), "l"(hf));             // 0.5(a+b)
    asm("fma.rn.f32x2 %0, %1, %2, %3;" : "=l"(lo) : "l"(k), "l"(nh), "l"(h));
    asm("fma.rn.f32x2 %0, %1, %2, %3;" : "=l"(hi) : "l"(k), "l"(hf), "l"(h));
}

__device__ __forceinline__ float med3(float a, float b, float c) {
    return fmaxf(fminf(a, b), fminf(fmaxf(a, b), c));
}

struct Row3 { u64 a, b, c; };   // packed columns (1,2) (3,4) (0,5)

__device__ __forceinline__ void emit_row(const Row3& pl, const Row3& ph,
                                         const Row3& t,
                                         float* __restrict__ dst) {
    float4 res;
    u64 loa, mia, hia, loc, mic, hic, tm;
    cex2(pl.a, t.a, loa, tm);
    cex2(ph.a, tm, mia, hia);
    cex2(pl.c, t.c, loc, tm);
    cex2(ph.c, tm, mic, hic);

    float2 la = upk(loa), lc = upk(loc);
    float2 ma = upk(mia), mc = upk(mic);
    float2 ha = upk(hia), hc = upk(hic);

    float sA  = fmaxf(la.x, la.y);
    float tA  = fminf(ha.x, ha.y);
    float q0A = fminf(ma.x, ma.y), q1A = fmaxf(ma.x, ma.y);

    u64 lob, mib, hib;
    cex2(pl.b, t.b, lob, tm);
    cex2(ph.b, tm, mib, hib);
    float2 lb = upk(lob), mb = upk(mib), hb = upk(hib);

    res.x = med3(fmaxf(lc.x, sA),
                 fmaxf(q0A, fminf(q1A, mc.x)),
                 fminf(hc.x, tA));
    res.y = med3(fmaxf(sA, lb.x),
                 fmaxf(q0A, fminf(q1A, mb.x)),
                 fminf(tA, hb.x));

    float sB  = fmaxf(lb.x, lb.y);
    float tB  = fminf(hb.x, hb.y);
    float q0B = fminf(mb.x, mb.y), q1B = fmaxf(mb.x, mb.y);

    res.z = med3(fmaxf(la.y, sB),
                 fmaxf(q0B, fminf(q1B, ma.y)),
                 fminf(ha.y, tB));
    res.w = med3(fmaxf(sB, lc.y),
                 fmaxf(q0B, fminf(q1B, mc.y)),
                 fminf(tB, hc.y));

    *reinterpret_cast<float4*>(dst) = res;
}

__global__ __launch_bounds__(128, 10)
void median3x3_kernel(const float* __restrict__ x, float* __restrict__ out) {
    const int tid   = threadIdx.x;        // 0..127
    const int lane  = tid & 31;
    const int w0    = tid << 2;

    // block -> strip of K_TILES consecutive row-pair tiles in one plane
    const u32 t0    = blockIdx.x * K_TILES;         // 64 blocks per plane
    const u32 plane = t0 >> 8;                      // 0..47
    const int h0    = (int)(t0 & 255u) << 1;        // first output row

    const u32 base = plane * (u32)(H * W);

    // fixup column for the boundary lanes (reflect folded into the address)
    const u32 col = (lane == 0)
        ? ((w0 == 0) ? 1u : (u32)(w0 - 1))
        : ((w0 + 4 == W) ? (u32)(W - 2) : (u32)(w0 + 4));
    const bool edge = (lane == 0) | (lane == 31);

    // load a row and pack it into Row3 (vector body + shuffle halo + fixup)
    auto LOADPACK = [&](u32 o) -> Row3 {
        float4 q = *reinterpret_cast<const float4*>(x + o + w0);
        float fx;
        if (edge) fx = x[o + col];
        float l = __shfl_up_sync(0xffffffffu, q.w, 1);
        float e = __shfl_down_sync(0xffffffffu, q.x, 1);
        l = (lane == 0)  ? fx : l;
        e = (lane == 31) ? fx : e;
        Row3 f;
        f.a = pk(q.x, q.y);
        f.b = pk(q.z, q.w);
        f.c = pk(l, e);
        return f;
    };

    // preload carried rows: f0c = row h0-1 (reflected), f1c = row h0
    const u32 o1 = base + (u32)h0 * W;
    const u32 o0 = (h0 == 0) ? o1 + W : o1 - W;
    Row3 f0c = LOADPACK(o0);
    Row3 f1c = LOADPACK(o1);

    u32 orow = o1 + W;                    // row h+1 of current tile
    float* od = out + o1 + w0;

#pragma unroll 1
    for (int i = 0; i < K_TILES; i++) {
        const int h = h0 + 2 * i;
        const u32 o2 = orow;                                    // row h+1
        const u32 o3 = (h + 2 >= H) ? o2 - W : o2 + W;          // row h+2 (reflect)

        Row3 f2 = LOADPACK(o2);
        Row3 f3 = LOADPACK(o3);

        // pair = sort(f1c, f2); thirds f0c (row h-1) and f3 (row h+2)
        Row3 pl, ph;
        cex2(f1c.a, f2.a, pl.a, ph.a);
        cex2(f1c.b, f2.b, pl.b, ph.b);
        cex2(f1c.c, f2.c, pl.c, ph.c);

        emit_row(pl, ph, f0c, od);        // output row h
        emit_row(pl, ph, f3, od + W);     // output row h+1

        // carry rows h+1, h+2 as next tile's f0/f1
        f0c = f2;
        f1c = f3;
        orow += 2 * W;
        od   += 2 * W;
    }
}

extern "C" void kernel_launch(void* const* d_in, const int* in_sizes, int n_in,
                              void* d_out, int out_size) {
    const float* x = (const float*)d_in[0];
    float* out = (float*)d_out;
    dim3 grid((256 / K_TILES) * 48);   // 64 strips/plane * 48 planes = 3072
    dim3 block(128);
    median3x3_kernel<<<grid, block>>>(x, out);
}

// round 16
// speedup vs baseline: 1.0784x; 1.0784x over previous
#include <cuda_runtime.h>

// MedianPool2d 3x3, stride 1, reflect pad (1,1,1,1)
// float32 [16, 3, 512, 512] -> same shape.
//
// R16 = champion R7 per-thread body (4Wx2H, 40 regs, SHFL halos, packed f32x2
// vertical stage on FMA pipe + scalar FMNMX horizontal combine on ALU pipe),
// with 256-thread blocks covering TWO vertically adjacent row-pair tiles:
//   warps 0-3: output rows h0, h0+1     warps 4-7: output rows h0+2, h0+3
// The two halves run concurrently on the same SM and share input rows
// h0+1 / h0+2 through L1 (previously separate blocks -> separate SMs -> L2).
// No serialization, no extra registers, no placement assumptions.

#define W 512
#define H 512

typedef unsigned long long u64;
typedef unsigned int u32;

__device__ __forceinline__ u64 pk(float x, float y) {
    u64 r; asm("mov.b64 %0, {%1, %2};" : "=l"(r) : "f"(x), "f"(y)); return r;
}
__device__ __forceinline__ float2 upk(u64 v) {
    float2 f; asm("mov.b64 {%0, %1}, %2;" : "=f"(f.x), "=f"(f.y) : "l"(v)); return f;
}

// packed compare-exchange on 2 fp32 lanes: lo=min, hi=max (FMA pipe)
__device__ __forceinline__ void cex2(u64 a, u64 b, u64& lo, u64& hi) {
    const u64 n1 = 0xBF800000BF800000ULL;
    const u64 hf = 0x3F0000003F000000ULL;
    const u64 nh = 0xBF000000BF000000ULL;
    u64 s, d, k, h;
    asm("add.rn.f32x2 %0, %1, %2;" : "=l"(s) : "l"(a), "l"(b));
    asm("fma.rn.f32x2 %0, %1, %2, %3;" : "=l"(d) : "l"(b), "l"(n1), "l"(a)); // a-b
    k = d & 0x7FFFFFFF7FFFFFFFULL;                                           // |a-b|
    asm("mul.rn.f32x2 %0, %1, %2;" : "=l"(h) : "l"(s), "l"(hf));             // 0.5(a+b)
    asm("fma.rn.f32x2 %0, %1, %2, %3;" : "=l"(lo) : "l"(k), "l"(nh), "l"(h));
    asm("fma.rn.f32x2 %0, %1, %2, %3;" : "=l"(hi) : "l"(k), "l"(hf), "l"(h));
}

__device__ __forceinline__ float med3(float a, float b, float c) {
    return fmaxf(fminf(a, b), fminf(fmaxf(a, b), c));
}

struct Row3 { u64 a, b, c; };   // packed columns (1,2) (3,4) (0,5)

__device__ __forceinline__ void emit_row(const Row3& pl, const Row3& ph,
                                         const Row3& t,
                                         float* __restrict__ dst) {
    float4 res;
    u64 loa, mia, hia, loc, mic, hic, tm;
    cex2(pl.a, t.a, loa, tm);
    cex2(ph.a, tm, mia, hia);
    cex2(pl.c, t.c, loc, tm);
    cex2(ph.c, tm, mic, hic);

    float2 la = upk(loa), lc = upk(loc);
    float2 ma = upk(mia), mc = upk(mic);
    float2 ha = upk(hia), hc = upk(hic);

    float sA  = fmaxf(la.x, la.y);
    float tA  = fminf(ha.x, ha.y);
    float q0A = fminf(ma.x, ma.y), q1A = fmaxf(ma.x, ma.y);

    u64 lob, mib, hib;
    cex2(pl.b, t.b, lob, tm);
    cex2(ph.b, tm, mib, hib);
    float2 lb = upk(lob), mb = upk(mib), hb = upk(hib);

    res.x = med3(fmaxf(lc.x, sA),
                 fmaxf(q0A, fminf(q1A, mc.x)),
                 fminf(hc.x, tA));
    res.y = med3(fmaxf(sA, lb.x),
                 fmaxf(q0A, fminf(q1A, mb.x)),
                 fminf(tA, hb.x));

    float sB  = fmaxf(lb.x, lb.y);
    float tB  = fminf(hb.x, hb.y);
    float q0B = fminf(mb.x, mb.y), q1B = fmaxf(mb.x, mb.y);

    res.z = med3(fmaxf(la.y, sB),
                 fmaxf(q0B, fminf(q1B, ma.y)),
                 fminf(ha.y, tB));
    res.w = med3(fmaxf(sB, lc.y),
                 fmaxf(q0B, fminf(q1B, mc.y)),
                 fminf(tB, hc.y));

    *reinterpret_cast<float4*>(dst) = res;
}

__global__ __launch_bounds__(256, 6)
void median3x3_kernel(const float* __restrict__ x, float* __restrict__ out) {
    const int tid   = threadIdx.x;            // 0..255
    const int lane  = tid & 31;
    const int half  = tid >> 7;               // 0: rows h0,h0+1  1: rows h0+2,h0+3
    const int h0    = (int)(blockIdx.x << 2) + (half << 1);
    const u32 plane = blockIdx.y;              // 0..47
    const int w0    = (tid & 127) << 2;

    const u32 base = plane * (u32)(H * W);

    // frame rows f0..f3 = input rows h0-1 .. h0+2 (reflected at edges)
    const u32 o1 = base + (u32)h0 * W;
    const u32 o2 = o1 + W;
    const u32 o0 = (h0 == 0)     ? o2 : o1 - W;   // reflect row -1 -> 1
    const u32 o3 = (h0 + 2 >= H) ? o1 : o2 + W;   // reflect row H -> H-2

    // 4 vector loads, back-to-back
    float4 q0 = *reinterpret_cast<const float4*>(x + o0 + w0);
    float4 q1 = *reinterpret_cast<const float4*>(x + o1 + w0);
    float4 q2 = *reinterpret_cast<const float4*>(x + o2 + w0);
    float4 q3 = *reinterpret_cast<const float4*>(x + o3 + w0);

    // halo exchange via shuffle; boundary lanes fix up with loads
    float l0 = __shfl_up_sync(0xffffffffu, q0.w, 1);
    float l1 = __shfl_up_sync(0xffffffffu, q1.w, 1);
    float l2 = __shfl_up_sync(0xffffffffu, q2.w, 1);
    float l3 = __shfl_up_sync(0xffffffffu, q3.w, 1);
    float e0 = __shfl_down_sync(0xffffffffu, q0.x, 1);
    float e1 = __shfl_down_sync(0xffffffffu, q1.x, 1);
    float e2 = __shfl_down_sync(0xffffffffu, q2.x, 1);
    float e3 = __shfl_down_sync(0xffffffffu, q3.x, 1);

    if (lane == 0) {
        if (w0 == 0) {
            l0 = q0.y; l1 = q1.y; l2 = q2.y; l3 = q3.y;     // reflect: wl = 1
        } else {
            l0 = x[o0 + w0 - 1]; l1 = x[o1 + w0 - 1];
            l2 = x[o2 + w0 - 1]; l3 = x[o3 + w0 - 1];
        }
    }
    if (lane == 31) {
        if (w0 + 4 == W) {
            e0 = q0.z; e1 = q1.z; e2 = q2.z; e3 = q3.z;     // reflect: wr = W-2
        } else {
            e0 = x[o0 + w0 + 4]; e1 = x[o1 + w0 + 4];
            e2 = x[o2 + w0 + 4]; e3 = x[o3 + w0 + 4];
        }
    }

    Row3 f0, f1, f2, f3;
    f0.a = pk(q0.x, q0.y); f0.b = pk(q0.z, q0.w); f0.c = pk(l0, e0);
    f1.a = pk(q1.x, q1.y); f1.b = pk(q1.z, q1.w); f1.c = pk(l1, e1);
    f2.a = pk(q2.x, q2.y); f2.b = pk(q2.z, q2.w); f2.c = pk(l2, e2);
    f3.a = pk(q3.x, q3.y); f3.b = pk(q3.z, q3.w); f3.c = pk(l3, e3);

    // pair sort rows f1,f2 (both die afterward)
    Row3 pl, ph;
    cex2(f1.a, f2.a, pl.a, ph.a);
    cex2(f1.b, f2.b, pl.b, ph.b);
    cex2(f1.c, f2.c, pl.c, ph.c);

    float* o = out + o1 + w0;
    emit_row(pl, ph, f0, o);        // output row h0
    emit_row(pl, ph, f3, o + W);    // output row h0+1
}

extern "C" void kernel_launch(void* const* d_in, const int* in_sizes, int n_in,
                              void* d_out, int out_size) {
    const float* x = (const float*)d_in[0];
    float* out = (float*)d_out;
    dim3 grid(H / 4, 48);    // 128 row-quads x 48 planes = 6144 blocks
    dim3 block(256);         // two row-pair tiles per block (same SM, shared L1)
    median3x3_kernel<<<grid, block>>>(x, out);
}

// round 17
// speedup vs baseline: 1.1969x; 1.1099x over previous
#include <cuda_runtime.h>

// MedianPool2d 3x3, stride 1, reflect pad (1,1,1,1)
// float32 [16, 3, 512, 512] -> same shape.
//
// CHAMPION (R7, bench 20.93us): 4(W) x 2(H) outputs per thread.
// - Vertical stage (row-pair sort + third-row merge) on the FMA pipe via
//   packed f32x2 arithmetic compare-exchange (lo/hi = 0.5(a+b) -/+ 0.5|a-b|),
//   two column-pairs per instruction.
// - Horizontal combine: scalar FMNMX sliding-window network (ALU pipe);
//   median9 = med3(max-of-lows, med3-of-mids, min-of-highs).
// - Halo columns via warp shuffle (lane 0/31 fix up with predicated loads;
//   global reflect edges reuse in-register values: wl=1 -> q.y, wr=W-2 -> q.z).
// - 32-bit offset addressing; 40 regs; occupancy 64%.
// Rounds 8-16 falsified all remaining levers (bigger tiles, pipelining,
// placement, row-carry, fat blocks) — this configuration is the measured
// optimum on the 40-reg / occ-64% frontier.

#define W 512
#define H 512

typedef unsigned long long u64;
typedef unsigned int u32;

__device__ __forceinline__ u64 pk(float x, float y) {
    u64 r; asm("mov.b64 %0, {%1, %2};" : "=l"(r) : "f"(x), "f"(y)); return r;
}
__device__ __forceinline__ float2 upk(u64 v) {
    float2 f; asm("mov.b64 {%0, %1}, %2;" : "=f"(f.x), "=f"(f.y) : "l"(v)); return f;
}

// packed compare-exchange on 2 fp32 lanes: lo=min, hi=max
__device__ __forceinline__ void cex2(u64 a, u64 b, u64& lo, u64& hi) {
    const u64 n1 = 0xBF800000BF800000ULL;
    const u64 hf = 0x3F0000003F000000ULL;
    const u64 nh = 0xBF000000BF000000ULL;
    u64 s, d, k, h;
    asm("add.rn.f32x2 %0, %1, %2;" : "=l"(s) : "l"(a), "l"(b));
    asm("fma.rn.f32x2 %0, %1, %2, %3;" : "=l"(d) : "l"(b), "l"(n1), "l"(a)); // a-b
    k = d & 0x7FFFFFFF7FFFFFFFULL;                                           // |a-b|
    asm("mul.rn.f32x2 %0, %1, %2;" : "=l"(h) : "l"(s), "l"(hf));             // 0.5(a+b)
    asm("fma.rn.f32x2 %0, %1, %2, %3;" : "=l"(lo) : "l"(k), "l"(nh), "l"(h));
    asm("fma.rn.f32x2 %0, %1, %2, %3;" : "=l"(hi) : "l"(k), "l"(hf), "l"(h));
}

__device__ __forceinline__ float med3(float a, float b, float c) {
    return fmaxf(fminf(a, b), fminf(fmaxf(a, b), c));
}

struct Row3 { u64 a, b, c; };   // packed columns (1,2) (3,4) (0,5)

__device__ __forceinline__ void emit_row(const Row3& pl, const Row3& ph,
                                         const Row3& t,
                                         float* __restrict__ dst) {
    float4 res;
    u64 loa, mia, hia, loc, mic, hic, tm;
    cex2(pl.a, t.a, loa, tm);
    cex2(ph.a, tm, mia, hia);
    cex2(pl.c, t.c, loc, tm);
    cex2(ph.c, tm, mic, hic);

    float2 la = upk(loa), lc = upk(loc);
    float2 ma = upk(mia), mc = upk(mic);
    float2 ha = upk(hia), hc = upk(hic);

    float sA  = fmaxf(la.x, la.y);
    float tA  = fminf(ha.x, ha.y);
    float q0A = fminf(ma.x, ma.y), q1A = fmaxf(ma.x, ma.y);

    u64 lob, mib, hib;
    cex2(pl.b, t.b, lob, tm);
    cex2(ph.b, tm, mib, hib);
    float2 lb = upk(lob), mb = upk(mib), hb = upk(hib);

    res.x = med3(fmaxf(lc.x, sA),
                 fmaxf(q0A, fminf(q1A, mc.x)),
                 fminf(hc.x, tA));
    res.y = med3(fmaxf(sA, lb.x),
                 fmaxf(q0A, fminf(q1A, mb.x)),
                 fminf(tA, hb.x));

    float sB  = fmaxf(lb.x, lb.y);
    float tB  = fminf(hb.x, hb.y);
    float q0B = fminf(mb.x, mb.y), q1B = fmaxf(mb.x, mb.y);

    res.z = med3(fmaxf(la.y, sB),
                 fmaxf(q0B, fminf(q1B, ma.y)),
                 fminf(ha.y, tB));
    res.w = med3(fmaxf(sB, lc.y),
                 fmaxf(q0B, fminf(q1B, mc.y)),
                 fminf(tB, hc.y));

    *reinterpret_cast<float4*>(dst) = res;
}

__global__ __launch_bounds__(128, 12)
void median3x3_kernel(const float* __restrict__ x, float* __restrict__ out) {
    const int tid   = threadIdx.x;        // 0..127
    const int lane  = tid & 31;
    const int h0    = blockIdx.x << 1;    // 2 output rows per block
    const u32 plane = blockIdx.y;         // 0..47
    const int w0    = tid << 2;

    const u32 base = plane * (u32)(H * W);

    // frame rows f0..f3 = input rows h0-1 .. h0+2 (reflected at edges)
    const int hr0 = (h0 == 0)     ? 1     : h0 - 1;
    const int hr3 = (h0 + 2 >= H) ? H - 2 : h0 + 2;

    const u32 o0 = base + (u32)hr0 * W;
    const u32 o1 = base + (u32)h0  * W;
    const u32 o2 = o1 + W;
    const u32 o3 = base + (u32)hr3 * W;

    // vector loads up front (4 LDG.128 in flight)
    float4 q0 = *reinterpret_cast<const float4*>(x + o0 + w0);
    float4 q1 = *reinterpret_cast<const float4*>(x + o1 + w0);
    float4 q2 = *reinterpret_cast<const float4*>(x + o2 + w0);
    float4 q3 = *reinterpret_cast<const float4*>(x + o3 + w0);

    // halo exchange via shuffle; boundary lanes fix up with predicated LDG.
    float l0 = __shfl_up_sync(0xffffffffu, q0.w, 1);
    float l1 = __shfl_up_sync(0xffffffffu, q1.w, 1);
    float l2 = __shfl_up_sync(0xffffffffu, q2.w, 1);
    float l3 = __shfl_up_sync(0xffffffffu, q3.w, 1);
    float e0 = __shfl_down_sync(0xffffffffu, q0.x, 1);
    float e1 = __shfl_down_sync(0xffffffffu, q1.x, 1);
    float e2 = __shfl_down_sync(0xffffffffu, q2.x, 1);
    float e3 = __shfl_down_sync(0xffffffffu, q3.x, 1);

    if (lane == 0) {
        if (w0 == 0) {
            l0 = q0.y; l1 = q1.y; l2 = q2.y; l3 = q3.y;     // reflect: wl = 1
        } else {
            l0 = x[o0 + w0 - 1]; l1 = x[o1 + w0 - 1];
            l2 = x[o2 + w0 - 1]; l3 = x[o3 + w0 - 1];
        }
    }
    if (lane == 31) {
        if (w0 + 4 == W) {
            e0 = q0.z; e1 = q1.z; e2 = q2.z; e3 = q3.z;     // reflect: wr = W-2
        } else {
            e0 = x[o0 + w0 + 4]; e1 = x[o1 + w0 + 4];
            e2 = x[o2 + w0 + 4]; e3 = x[o3 + w0 + 4];
        }
    }

    Row3 f0, f1, f2, f3;
    f0.a = pk(q0.x, q0.y); f0.b = pk(q0.z, q0.w); f0.c = pk(l0, e0);
    f1.a = pk(q1.x, q1.y); f1.b = pk(q1.z, q1.w); f1.c = pk(l1, e1);
    f2.a = pk(q2.x, q2.y); f2.b = pk(q2.z, q2.w); f2.c = pk(l2, e2);
    f3.a = pk(q3.x, q3.y); f3.b = pk(q3.z, q3.w); f3.c = pk(l3, e3);

    // pair sort rows f1,f2 (both die afterward)
    Row3 pl, ph;
    cex2(f1.a, f2.a, pl.a, ph.a);
    cex2(f1.b, f2.b, pl.b, ph.b);
    cex2(f1.c, f2.c, pl.c, ph.c);

    float* o = out + o1 + w0;
    emit_row(pl, ph, f0, o);        // output row h0
    emit_row(pl, ph, f3, o + W);    // output row h0+1
}

extern "C" void kernel_launch(void* const* d_in, const int* in_sizes, int n_in,
                              void* d_out, int out_size) {
    const float* x = (const float*)d_in[0];
    float* out = (float*)d_out;
    dim3 grid(H / 2, 48);    // 256 row-pairs x 48 planes = 12288 blocks
    dim3 block(128);
    median3x3_kernel<<<grid, block>>>(x, out);
}